// round 14
// baseline (speedup 1.0000x reference)
#include <cuda_runtime.h>
#include <cuda_bf16.h>
#include <cstdint>

#define BATCHN 32
#define SEQ    1024
#define DIM    128
#define KC     64
#define NITER  (SEQ / KC)
#define PK     136

__device__ uint4 g_nbf4[BATCHN * SEQ * DIM / 8];
__device__ uint4 g_wbf4[DIM * DIM / 8];
__device__ uint4 g_bh4[DIM * DIM / 8];
__device__ uint4 g_bl4[DIM * DIM / 8];

// ---------------- helpers ----------------
__device__ __forceinline__ unsigned smaddr(const void* p) {
    return (unsigned)__cvta_generic_to_shared(p);
}
__device__ __forceinline__ void ldsm4(unsigned* r, unsigned a) {
    asm volatile("ldmatrix.sync.aligned.m8n8.x4.shared.b16 {%0,%1,%2,%3},[%4];"
                 : "=r"(r[0]), "=r"(r[1]), "=r"(r[2]), "=r"(r[3]) : "r"(a));
}
__device__ __forceinline__ void ldsm4t(unsigned* r, unsigned a) {
    asm volatile("ldmatrix.sync.aligned.m8n8.x4.trans.shared.b16 {%0,%1,%2,%3},[%4];"
                 : "=r"(r[0]), "=r"(r[1]), "=r"(r[2]), "=r"(r[3]) : "r"(a));
}
__device__ __forceinline__ void mma16816(float* c, const unsigned* a, const unsigned* b) {
    asm volatile("mma.sync.aligned.m16n8k16.row.col.f32.bf16.bf16.f32 "
                 "{%0,%1,%2,%3},{%4,%5,%6,%7},{%8,%9},{%0,%1,%2,%3};"
                 : "+f"(c[0]), "+f"(c[1]), "+f"(c[2]), "+f"(c[3])
                 : "r"(a[0]), "r"(a[1]), "r"(a[2]), "r"(a[3]), "r"(b[0]), "r"(b[1]));
}
__device__ __forceinline__ unsigned packbf(float lo, float hi) {
    unsigned r;
    asm("cvt.rn.bf16x2.f32 %0, %1, %2;" : "=r"(r) : "f"(hi), "f"(lo));
    return r;
}
__device__ __forceinline__ void cpa16(unsigned s, const void* g) {
    asm volatile("cp.async.cg.shared.global [%0], [%1], 16;" :: "r"(s), "l"(g) : "memory");
}
__device__ __forceinline__ void cp_commit() {
    asm volatile("cp.async.commit_group;" ::: "memory");
}
__device__ __forceinline__ float lrelu(float x) { return x >= 0.f ? x : 0.1f * x; }
__device__ __forceinline__ float bfh(float x) {
    return __bfloat162float(__float2bfloat16_rn(x));
}
__device__ __forceinline__ uint4 pack4(float4 a, float4 b) {
    return make_uint4(packbf(a.x, a.y), packbf(a.z, a.w),
                      packbf(b.x, b.y), packbf(b.z, b.w));
}

// ---------------- fused prep kernel ----------------
// blocks [0,2048): nodes -> bf16 hi; blocks [2048,2080): W/B -> bf16 (+B lo split)
__global__ void prep_all(const float* __restrict__ nodes, const float* __restrict__ Wm,
                         const float* __restrict__ Bm) {
    int blk = blockIdx.x;
    if (blk < 2048) {
        long long i = ((long long)blk * 256 + threadIdx.x) * 8;
        float4 v0 = *(const float4*)(nodes + i);
        float4 v1 = *(const float4*)(nodes + i + 4);
        uint4 hi = make_uint4(packbf(bfh(v0.x), bfh(v0.y)), packbf(bfh(v0.z), bfh(v0.w)),
                              packbf(bfh(v1.x), bfh(v1.y)), packbf(bfh(v1.z), bfh(v1.w)));
        *(uint4*)((__nv_bfloat16*)g_nbf4 + i) = hi;
    } else {
        int q = (blk - 2048) * 256 + threadIdx.x;
        if (q < 4096) {
            long long i = (long long)q * 4;
            float4 w = *(const float4*)(Wm + i);
            *(uint2*)((__nv_bfloat16*)g_wbf4 + i) =
                make_uint2(packbf(w.x, w.y), packbf(w.z, w.w));
        } else {
            long long i = (long long)(q - 4096) * 4;
            float4 v = *(const float4*)(Bm + i);
            float hx = bfh(v.x), hy = bfh(v.y), hz = bfh(v.z), hw = bfh(v.w);
            *(uint2*)((__nv_bfloat16*)g_bh4 + i) = make_uint2(packbf(hx, hy), packbf(hz, hw));
            *(uint2*)((__nv_bfloat16*)g_bl4 + i) =
                make_uint2(packbf(v.x - hx, v.y - hy), packbf(v.z - hz, v.w - hw));
        }
    }
}

// smem map (bytes):
//  phase1: mask 2 stages @0      (2 x 17408 = 34816)  [64 o-rows x PK bf16]
//          nodes 2 stages @34816 (2 x 17408 = 34816)  -> [0, 69632)
//  P bf16 [128][PK] @69632 (34816)                    -> [69632, 104448)
//  phase2: 2 chunk stages @0, each 25344 (W/Bh/Bl 16x272B, SH/SL 128x48B) -> [0,50688)
#define OFF_NODE 34816
#define OFF_P    69632
#define STG1     17408
#define STGSZ    25344
#define C_W      0
#define C_BH     4352
#define C_BL     8704
#define C_SH     13056
#define C_SL     19200
#define CH       16
#define NCH      8
#define SMEM_SZ  104448

__global__ __launch_bounds__(256, 2)
void gcn_fused_kernel(const float* __restrict__ nodes, const int* __restrict__ adj,
                      float* __restrict__ out)
{
    extern __shared__ __align__(16) unsigned char smem[];
    __shared__ int scnt[128];

    const int t    = threadIdx.x;
    const int lane = t & 31;
    const int wid  = t >> 5;
    const int wm   = wid >> 1;     // 0..3 : owns 32 i-rows
    const int wn   = wid & 1;      // 0..1 : owns 64 d-cols
    const int b    = blockIdx.y;
    const int i0   = blockIdx.x * 128;

    if (t < 128) scnt[t] = 0;

    const int* adjBase = adj + (long long)b * SEQ * SEQ + i0 + 4 * lane;
    const __nv_bfloat16* nbfB = (const __nv_bfloat16*)g_nbf4 + (long long)b * SEQ * DIM;
    const __nv_bfloat16* wbf  = (const __nv_bfloat16*)g_wbf4;
    const __nv_bfloat16* bhp  = (const __nv_bfloat16*)g_bh4;
    const __nv_bfloat16* blp  = (const __nv_bfloat16*)g_bl4;

    const unsigned maskSm = smaddr(smem);
    const unsigned nodeSm = smaddr(smem + OFF_NODE);
    const int ncRow = t >> 4, ncCol = t & 15;   // also used by phase-2 W staging

    // nodes stage = 64 rows x 272B; 4 chunks of 16B per thread
#define ISSUE_NODES(IT) do {                                                      \
        unsigned _sb = nodeSm + ((IT) & 1) * STG1;                                \
        const __nv_bfloat16* _g = nbfB + (IT) * KC * DIM;                         \
        _Pragma("unroll")                                                         \
        for (int _k = 0; _k < 4; _k++) {                                          \
            int _q = t + 256 * _k;                                                \
            int _r = _q >> 4, _cc = _q & 15;                                      \
            cpa16(_sb + _r * 272 + _cc * 16, _g + _r * DIM + _cc * 8);            \
        }                                                                         \
        cp_commit();                                                              \
    } while (0)

    ISSUE_NODES(0);

    // adj prefetch iter 0: thread owns rows o = wid + 8p (p<8), cols 4*lane..+3
    int4 mreg[8];
#pragma unroll
    for (int p = 0; p < 8; p++)
        mreg[p] = *(const int4*)(adjBase + (long long)(wid + 8 * p) * SEQ);

    float c[64];
#pragma unroll
    for (int i = 0; i < 64; i++) c[i] = 0.f;
    int cnt0 = 0, cnt1 = 0, cnt2 = 0, cnt3 = 0;

    // ldmatrix offsets
    const unsigned aRow  = (lane & 7) + ((lane >> 4) & 1) * 8;
    const unsigned aCol8 = ((lane >> 3) & 1) * 8;
    const unsigned bRow  = (lane & 7) + ((lane >> 3) & 1) * 8;
    const unsigned bCol8 = ((lane >> 4) & 1) * 8;
    const unsigned bOff  = (bRow * PK + bCol8) * 2;

    for (int it = 0; it < NITER; ++it) {
        // ---- produce mask stage (it&1) + counts ----
        unsigned mst = (it & 1) * STG1;
#pragma unroll
        for (int p = 0; p < 8; p++) {
            int o = wid + 8 * p;
            int4 m = mreg[p];
            cnt0 += (m.x != 0); cnt1 += (m.y != 0); cnt2 += (m.z != 0); cnt3 += (m.w != 0);
            unsigned lo = (m.x ? 0x3F80u : 0u) | (m.y ? 0x3F800000u : 0u);
            unsigned hi = (m.z ? 0x3F80u : 0u) | (m.w ? 0x3F800000u : 0u);
            *(uint2*)(smem + mst + (o * PK + 4 * lane) * 2) = make_uint2(lo, hi);
        }
        // ---- prefetch adj(it+1) (overlaps MMA below) ----
        if (it + 1 < NITER) {
            const int* ab = adjBase + (long long)(it + 1) * KC * SEQ;
#pragma unroll
            for (int p = 0; p < 8; p++)
                mreg[p] = *(const int4*)(ab + (long long)(wid + 8 * p) * SEQ);
        }
        asm volatile("cp.async.wait_group 0;" ::: "memory");   // nodes stage it ready
        __syncthreads();                                       // mask + nodes visible
        // issue next node stage: buffer (it+1)&1 last consumed at it-1; all warps
        // passed sync(it) => consumption done. Arrives during consume(it).
        if (it + 1 < NITER) ISSUE_NODES(it + 1);

        // ---- consume: 2D warp tile 32i x 64d, 4 k-steps of 16 ----
        const unsigned mA = maskSm + (it & 1) * STG1;
        const unsigned nB = nodeSm + (it & 1) * STG1;
#pragma unroll
        for (int kk = 0; kk < 4; kk++) {
            unsigned a0[4], a1[4];
            ldsm4t(a0, mA + ((kk * 16 + aRow) * PK + wm * 32 + aCol8) * 2);
            ldsm4t(a1, mA + ((kk * 16 + aRow) * PK + wm * 32 + 16 + aCol8) * 2);
#pragma unroll
            for (int ng = 0; ng < 4; ng++) {
                unsigned bb[4];
                ldsm4t(bb, nB + ((kk * 16 + bRow) * PK + wn * 64 + ng * 16 + bCol8) * 2);
                mma16816(c + (2 * ng + 0) * 4,     a0, bb);
                mma16816(c + (2 * ng + 1) * 4,     a0, bb + 2);
                mma16816(c + (8 + 2 * ng + 0) * 4, a1, bb);
                mma16816(c + (8 + 2 * ng + 1) * 4, a1, bb + 2);
            }
        }
    }

    atomicAdd(&scnt[4 * lane + 0], cnt0);
    atomicAdd(&scnt[4 * lane + 1], cnt1);
    atomicAdd(&scnt[4 * lane + 2], cnt2);
    atomicAdd(&scnt[4 * lane + 3], cnt3);
    __syncthreads();   // scnt valid; phase-1 smem dead; no cp.async pending

    // ================= phase 2 =================
    const float* selfF = nodes + ((long long)b * SEQ + i0 + (t >> 1)) * DIM + (t & 1) * 8;

#define ISSUE_W(JC) do {                                                          \
        unsigned _st = maskSm + ((JC) & 1) * STGSZ;                               \
        unsigned _so = ncRow * 272 + ncCol * 16;                                  \
        int _go = ((JC) * CH + ncRow) * DIM + ncCol * 8;                          \
        cpa16(_st + C_W  + _so, wbf + _go);                                      \
        cpa16(_st + C_BH + _so, bhp + _go);                                      \
        cpa16(_st + C_BL + _so, blp + _go);                                      \
        cp_commit();                                                              \
    } while (0)

#define STS_SELF(JC, VA, VB) do {                                                 \
        unsigned char* _p = smem + ((JC) & 1) * STGSZ;                            \
        float _h0 = bfh((VA).x), _h1 = bfh((VA).y), _h2 = bfh((VA).z), _h3 = bfh((VA).w); \
        float _h4 = bfh((VB).x), _h5 = bfh((VB).y), _h6 = bfh((VB).z), _h7 = bfh((VB).w); \
        *(uint4*)(_p + C_SH + (t >> 1) * 48 + (t & 1) * 16) =                     \
            make_uint4(packbf(_h0, _h1), packbf(_h2, _h3),                        \
                       packbf(_h4, _h5), packbf(_h6, _h7));                       \
        *(uint4*)(_p + C_SL + (t >> 1) * 48 + (t & 1) * 16) =                     \
            make_uint4(packbf((VA).x - _h0, (VA).y - _h1),                        \
                       packbf((VA).z - _h2, (VA).w - _h3),                        \
                       packbf((VB).x - _h4, (VB).y - _h5),                        \
                       packbf((VB).z - _h6, (VB).w - _h7));                       \
    } while (0)

    // prologue: kick W/B chunks 0,1; load self fp32 for 0,1; normalize P meanwhile
    float4 s0a = *(const float4*)(selfF + 0);
    float4 s0b = *(const float4*)(selfF + 4);
    float4 s1a = *(const float4*)(selfF + 16);
    float4 s1b = *(const float4*)(selfF + 20);
    ISSUE_W(0);
    ISSUE_W(1);

    {
        const int rBase = wm * 32 + (lane >> 2);
        const float i00 = 1.f / fmaxf((float)scnt[rBase], 1.f);
        const float i01 = 1.f / fmaxf((float)scnt[rBase + 8], 1.f);
        const float i10 = 1.f / fmaxf((float)scnt[rBase + 16], 1.f);
        const float i11 = 1.f / fmaxf((float)scnt[rBase + 24], 1.f);
        unsigned char* P = smem + OFF_P;
        const int colB = wn * 64 + 2 * (lane & 3);
#pragma unroll
        for (int mt = 0; mt < 2; mt++) {
            const float ivA = mt ? i10 : i00;
            const float ivB = mt ? i11 : i01;
            const int r0 = rBase + mt * 16;
#pragma unroll
            for (int nn = 0; nn < 8; nn++) {
                float* cc = c + (mt * 8 + nn) * 4;
                const int col = colB + nn * 8;
                *(unsigned*)(P + (r0 * PK + col) * 2)       = packbf(cc[0] * ivA, cc[1] * ivA);
                *(unsigned*)(P + ((r0 + 8) * PK + col) * 2) = packbf(cc[2] * ivB, cc[3] * ivB);
            }
        }
    }
    STS_SELF(0, s0a, s0b);
    STS_SELF(1, s1a, s1b);

#pragma unroll
    for (int i = 0; i < 64; i++) c[i] = 0.f;

    const unsigned aS2     = ((wid * 16 + (lane & 15)) * 24 + ((lane >> 4) & 1) * 8) * 2;
    const unsigned aP_base = ((wid * 16 + (lane & 15)) * PK + ((lane >> 4) & 1) * 8) * 2;
    const unsigned Psm = maskSm + OFF_P;

    float4 pa, pb;
#pragma unroll 1
    for (int jc = 0; jc < NCH; ++jc) {
        if (jc == NCH - 1) asm volatile("cp.async.wait_group 0;" ::: "memory");
        else               asm volatile("cp.async.wait_group 1;" ::: "memory");
        __syncthreads();   // chunk jc (cp.async W/B + self STS) visible

        if (jc + 2 < NCH) {
            pa = *(const float4*)(selfF + (jc + 2) * CH);
            pb = *(const float4*)(selfF + (jc + 2) * CH + 4);
        }

        const unsigned st = maskSm + (jc & 1) * STGSZ;
        unsigned aH[4], aL[4], aP[4];
        ldsm4(aH, st + C_SH + aS2);
        ldsm4(aL, st + C_SL + aS2);
        ldsm4(aP, Psm + aP_base + jc * CH * 2);
#pragma unroll
        for (int nb = 0; nb < 8; nb++) {
            const unsigned off = bOff + nb * 16 * 2;
            unsigned bW[4], bH[4], bL[4];
            ldsm4t(bW, st + C_W  + off);
            ldsm4t(bH, st + C_BH + off);
            ldsm4t(bL, st + C_BL + off);
            float* cc0 = c + 8 * nb;
            float* cc1 = c + 8 * nb + 4;
            mma16816(cc0, aP, bW);  mma16816(cc1, aP, bW + 2);
            mma16816(cc0, aH, bH);  mma16816(cc1, aH, bH + 2);
            mma16816(cc0, aH, bL);  mma16816(cc1, aH, bL + 2);
            mma16816(cc0, aL, bH);  mma16816(cc1, aL, bH + 2);
        }
        __syncthreads();   // stage (jc&1) free for reuse
        if (jc + 2 < NCH) {
            ISSUE_W(jc + 2);
            STS_SELF(jc + 2, pa, pb);
        }
    }

    const int orow = i0 + wid * 16 + (lane >> 2);
    const int ocol = 2 * (lane & 3);
    float* outB = out + ((long long)b * SEQ + orow) * DIM;
#pragma unroll
    for (int nt = 0; nt < 16; nt++) {
        int colx = 8 * nt + ocol;
        float2 v01 = make_float2(lrelu(c[4 * nt + 0]), lrelu(c[4 * nt + 1]));
        float2 v23 = make_float2(lrelu(c[4 * nt + 2]), lrelu(c[4 * nt + 3]));
        *(float2*)(outB + colx)           = v01;
        *(float2*)(outB + 8 * DIM + colx) = v23;
    }
}

extern "C" void kernel_launch(void* const* d_in, const int* in_sizes, int n_in,
                              void* d_out, int out_size)
{
    (void)in_sizes; (void)n_in; (void)out_size;
    const float* nodes = (const float*)d_in[0];
    const int*   adj   = (const int*)d_in[1];
    const float* Wm    = (const float*)d_in[2];
    const float* Bm    = (const float*)d_in[3];
    float*       out   = (float*)d_out;

    cudaFuncSetAttribute(gcn_fused_kernel,
                         cudaFuncAttributeMaxDynamicSharedMemorySize, SMEM_SZ);

    prep_all<<<2080, 256>>>(nodes, Wm, Bm);
    dim3 grid(SEQ / 128, BATCHN);
    gcn_fused_kernel<<<grid, 256, SMEM_SZ>>>(nodes, adj, out);
}

// round 16
// speedup vs baseline: 1.1587x; 1.1587x over previous
#include <cuda_runtime.h>
#include <cuda_bf16.h>
#include <cstdint>

#define BATCHN 32
#define SEQ    1024
#define DIM    128
#define KC     32
#define NITER  (SEQ / KC)
#define PK     136

__device__ uint4 g_nbf4[BATCHN * SEQ * DIM / 8];
__device__ uint4 g_wbf4[DIM * DIM / 8];
__device__ uint4 g_bh4[DIM * DIM / 8];
__device__ uint4 g_bl4[DIM * DIM / 8];

// ---------------- helpers ----------------
__device__ __forceinline__ unsigned smaddr(const void* p) {
    return (unsigned)__cvta_generic_to_shared(p);
}
__device__ __forceinline__ void ldsm4(unsigned* r, unsigned a) {
    asm volatile("ldmatrix.sync.aligned.m8n8.x4.shared.b16 {%0,%1,%2,%3},[%4];"
                 : "=r"(r[0]), "=r"(r[1]), "=r"(r[2]), "=r"(r[3]) : "r"(a));
}
__device__ __forceinline__ void ldsm4t(unsigned* r, unsigned a) {
    asm volatile("ldmatrix.sync.aligned.m8n8.x4.trans.shared.b16 {%0,%1,%2,%3},[%4];"
                 : "=r"(r[0]), "=r"(r[1]), "=r"(r[2]), "=r"(r[3]) : "r"(a));
}
__device__ __forceinline__ void mma16816(float* c, const unsigned* a, const unsigned* b) {
    asm volatile("mma.sync.aligned.m16n8k16.row.col.f32.bf16.bf16.f32 "
                 "{%0,%1,%2,%3},{%4,%5,%6,%7},{%8,%9},{%0,%1,%2,%3};"
                 : "+f"(c[0]), "+f"(c[1]), "+f"(c[2]), "+f"(c[3])
                 : "r"(a[0]), "r"(a[1]), "r"(a[2]), "r"(a[3]), "r"(b[0]), "r"(b[1]));
}
__device__ __forceinline__ unsigned packbf(float lo, float hi) {
    unsigned r;
    asm("cvt.rn.bf16x2.f32 %0, %1, %2;" : "=r"(r) : "f"(hi), "f"(lo));
    return r;
}
__device__ __forceinline__ void cpa16(unsigned s, const void* g) {
    asm volatile("cp.async.cg.shared.global [%0], [%1], 16;" :: "r"(s), "l"(g) : "memory");
}
__device__ __forceinline__ void cp_commit() {
    asm volatile("cp.async.commit_group;" ::: "memory");
}
__device__ __forceinline__ float lrelu(float x) { return x >= 0.f ? x : 0.1f * x; }
__device__ __forceinline__ float bfh(float x) {
    return __bfloat162float(__float2bfloat16_rn(x));
}
__device__ __forceinline__ uint4 pack4(float4 a, float4 b) {
    return make_uint4(packbf(a.x, a.y), packbf(a.z, a.w),
                      packbf(b.x, b.y), packbf(b.z, b.w));
}

// ---------------- fused prep kernel ----------------
// blocks [0,1024): nodes -> bf16 hi (16 floats/thread); blocks [1024,1056): W/B
__global__ void prep_all(const float* __restrict__ nodes, const float* __restrict__ Wm,
                         const float* __restrict__ Bm) {
    int blk = blockIdx.x;
    if (blk < 1024) {
        long long i = ((long long)blk * 256 + threadIdx.x) * 16;
        float4 v0 = *(const float4*)(nodes + i);
        float4 v1 = *(const float4*)(nodes + i + 4);
        float4 v2 = *(const float4*)(nodes + i + 8);
        float4 v3 = *(const float4*)(nodes + i + 12);
        __nv_bfloat16* dst = (__nv_bfloat16*)g_nbf4;
        *(uint4*)(dst + i)     = make_uint4(packbf(bfh(v0.x), bfh(v0.y)), packbf(bfh(v0.z), bfh(v0.w)),
                                            packbf(bfh(v1.x), bfh(v1.y)), packbf(bfh(v1.z), bfh(v1.w)));
        *(uint4*)(dst + i + 8) = make_uint4(packbf(bfh(v2.x), bfh(v2.y)), packbf(bfh(v2.z), bfh(v2.w)),
                                            packbf(bfh(v3.x), bfh(v3.y)), packbf(bfh(v3.z), bfh(v3.w)));
    } else {
        int q = (blk - 1024) * 256 + threadIdx.x;
        if (q < 4096) {
            long long i = (long long)q * 4;
            float4 w = *(const float4*)(Wm + i);
            *(uint2*)((__nv_bfloat16*)g_wbf4 + i) =
                make_uint2(packbf(w.x, w.y), packbf(w.z, w.w));
        } else {
            long long i = (long long)(q - 4096) * 4;
            float4 v = *(const float4*)(Bm + i);
            float hx = bfh(v.x), hy = bfh(v.y), hz = bfh(v.z), hw = bfh(v.w);
            *(uint2*)((__nv_bfloat16*)g_bh4 + i) = make_uint2(packbf(hx, hy), packbf(hz, hw));
            *(uint2*)((__nv_bfloat16*)g_bl4 + i) =
                make_uint2(packbf(v.x - hx, v.y - hy), packbf(v.z - hz, v.w - hw));
        }
    }
}

// smem map (bytes):
//  phase1: mask 2 stages @0 (17408) + nodes 4 stages @17408 (34816) -> [0, 52224)
//  P bf16 [128][PK] @52224 (34816)                                  -> [52224, 87040)
//  phase2: 2 chunk stages @0, each 25344 (W/Bh/Bl 16x272B, SH/SL 128x48B)
#define OFF_NODE 17408
#define OFF_P    52224
#define STGSZ    25344
#define C_W      0
#define C_BH     4352
#define C_BL     8704
#define C_SH     13056
#define C_SL     19200
#define CH       16
#define NCH      8
#define SMEM_SZ  87040

__global__ __launch_bounds__(256, 2)
void gcn_fused_kernel(const float* __restrict__ nodes, const int* __restrict__ adj,
                      float* __restrict__ out)
{
    extern __shared__ __align__(16) unsigned char smem[];
    __shared__ int scnt[128];

    const int t    = threadIdx.x;
    const int lane = t & 31;
    const int wid  = t >> 5;
    const int wm   = wid >> 1;     // 0..3 : owns 32 i-rows
    const int wn   = wid & 1;      // 0..1 : owns 64 d-cols
    const int b    = blockIdx.y;
    const int i0   = blockIdx.x * 128;

    if (t < 128) scnt[t] = 0;

    // mask staging coords: thread owns rows {mrow, mrow+16} x cols mcol..mcol+7
    const int mrow = t >> 4;            // 0..15
    const int mcol = (t & 15) * 8;      // 0,8,...,120
    const int* adjBase = adj + (long long)b * SEQ * SEQ + i0 + mcol;
    const __nv_bfloat16* nbfB = (const __nv_bfloat16*)g_nbf4 + (long long)b * SEQ * DIM;
    const __nv_bfloat16* wbf  = (const __nv_bfloat16*)g_wbf4;
    const __nv_bfloat16* bhp  = (const __nv_bfloat16*)g_bh4;
    const __nv_bfloat16* blp  = (const __nv_bfloat16*)g_bl4;

    const int ncRow0 = t >> 4,         ncCol0 = t & 15;
    const int ncRow1 = (t + 256) >> 4, ncCol1 = (t + 256) & 15;
    const unsigned nodeSm = smaddr(smem + OFF_NODE);
    const unsigned maskSm = smaddr(smem);

#define ISSUE_NODES(IT) do {                                                      \
        unsigned _sb = nodeSm + ((IT) & 3) * 8704;                                \
        const __nv_bfloat16* _g = nbfB + (IT) * KC * DIM;                         \
        cpa16(_sb + ncRow0 * 272 + ncCol0 * 16, _g + ncRow0 * DIM + ncCol0 * 8);  \
        cpa16(_sb + ncRow1 * 272 + ncCol1 * 16, _g + ncRow1 * DIM + ncCol1 * 8);  \
        cp_commit();                                                              \
    } while (0)

#define ISSUE_W(JC) do {                                                          \
        unsigned _st = maskSm + ((JC) & 1) * STGSZ;                               \
        unsigned _so = ncRow0 * 272 + ncCol0 * 16;                                \
        int _go = ((JC) * CH + ncRow0) * DIM + ncCol0 * 8;                        \
        cpa16(_st + C_W  + _so, wbf + _go);                                      \
        cpa16(_st + C_BH + _so, bhp + _go);                                      \
        cpa16(_st + C_BL + _so, blp + _go);                                      \
        cp_commit();                                                              \
    } while (0)

#define STS_SELF(JC, VA, VB) do {                                                 \
        unsigned char* _p = smem + ((JC) & 1) * STGSZ;                            \
        float _h0 = bfh((VA).x), _h1 = bfh((VA).y), _h2 = bfh((VA).z), _h3 = bfh((VA).w); \
        float _h4 = bfh((VB).x), _h5 = bfh((VB).y), _h6 = bfh((VB).z), _h7 = bfh((VB).w); \
        *(uint4*)(_p + C_SH + (t >> 1) * 48 + (t & 1) * 16) =                     \
            make_uint4(packbf(_h0, _h1), packbf(_h2, _h3),                        \
                       packbf(_h4, _h5), packbf(_h6, _h7));                       \
        *(uint4*)(_p + C_SL + (t >> 1) * 48 + (t & 1) * 16) =                     \
            make_uint4(packbf((VA).x - _h0, (VA).y - _h1),                        \
                       packbf((VA).z - _h2, (VA).w - _h3),                        \
                       packbf((VB).x - _h4, (VB).y - _h5),                        \
                       packbf((VB).z - _h6, (VB).w - _h7));                       \
    } while (0)

    ISSUE_NODES(0);
    ISSUE_NODES(1);

    // adj prefetch iter 0: 2 rows x 2 int4
    int4 mr0a, mr0b, mr1a, mr1b;
    mr0a = *(const int4*)(adjBase + (long long)mrow * SEQ);
    mr0b = *(const int4*)(adjBase + (long long)mrow * SEQ + 4);
    mr1a = *(const int4*)(adjBase + (long long)(mrow + 16) * SEQ);
    mr1b = *(const int4*)(adjBase + (long long)(mrow + 16) * SEQ + 4);

    float c[64];
#pragma unroll
    for (int i = 0; i < 64; i++) c[i] = 0.f;
    int cnt[8];
#pragma unroll
    for (int j = 0; j < 8; j++) cnt[j] = 0;

    // ldmatrix offsets
    const unsigned aRow  = (lane & 7) + ((lane >> 4) & 1) * 8;
    const unsigned aCol8 = ((lane >> 3) & 1) * 8;
    const unsigned bRow  = (lane & 7) + ((lane >> 3) & 1) * 8;
    const unsigned bCol8 = ((lane >> 4) & 1) * 8;
    const unsigned bOff  = (bRow * PK + bCol8) * 2;

    for (int it = 0; it < NITER; ++it) {
        // ---- produce mask stage (it&1) as 2 x STS.128 + counts ----
        {
            unsigned char* mp = smem + (it & 1) * 8704;
            cnt[0] += (mr0a.x != 0) + (mr1a.x != 0);
            cnt[1] += (mr0a.y != 0) + (mr1a.y != 0);
            cnt[2] += (mr0a.z != 0) + (mr1a.z != 0);
            cnt[3] += (mr0a.w != 0) + (mr1a.w != 0);
            cnt[4] += (mr0b.x != 0) + (mr1b.x != 0);
            cnt[5] += (mr0b.y != 0) + (mr1b.y != 0);
            cnt[6] += (mr0b.z != 0) + (mr1b.z != 0);
            cnt[7] += (mr0b.w != 0) + (mr1b.w != 0);
            *(uint4*)(mp + (mrow * PK + mcol) * 2) = make_uint4(
                (mr0a.x ? 0x3F80u : 0u) | (mr0a.y ? 0x3F800000u : 0u),
                (mr0a.z ? 0x3F80u : 0u) | (mr0a.w ? 0x3F800000u : 0u),
                (mr0b.x ? 0x3F80u : 0u) | (mr0b.y ? 0x3F800000u : 0u),
                (mr0b.z ? 0x3F80u : 0u) | (mr0b.w ? 0x3F800000u : 0u));
            *(uint4*)(mp + ((mrow + 16) * PK + mcol) * 2) = make_uint4(
                (mr1a.x ? 0x3F80u : 0u) | (mr1a.y ? 0x3F800000u : 0u),
                (mr1a.z ? 0x3F80u : 0u) | (mr1a.w ? 0x3F800000u : 0u),
                (mr1b.x ? 0x3F80u : 0u) | (mr1b.y ? 0x3F800000u : 0u),
                (mr1b.z ? 0x3F80u : 0u) | (mr1b.w ? 0x3F800000u : 0u));
        }
        // ---- prefetch adj(it+1) (overlaps MMA below) ----
        if (it + 1 < NITER) {
            const int* ab = adjBase + (long long)(it + 1) * KC * SEQ;
            mr0a = *(const int4*)(ab + (long long)mrow * SEQ);
            mr0b = *(const int4*)(ab + (long long)mrow * SEQ + 4);
            mr1a = *(const int4*)(ab + (long long)(mrow + 16) * SEQ);
            mr1b = *(const int4*)(ab + (long long)(mrow + 16) * SEQ + 4);
        }
        {
            int nx = it + 2;
            if (nx >= NITER) nx -= NITER;   // dead wrap keeps group FIFO uniform
            ISSUE_NODES(nx);
        }
        asm volatile("cp.async.wait_group 2;" ::: "memory");
        __syncthreads();

        // ---- consume stage: 2D warp tile 32i x 64d ----
        const unsigned mA = maskSm + (it & 1) * 8704;
        const unsigned nB = nodeSm + (it & 3) * 8704;
#pragma unroll
        for (int kk = 0; kk < 2; kk++) {
            unsigned a0[4], a1[4];
            ldsm4t(a0, mA + ((kk * 16 + aRow) * PK + wm * 32 + aCol8) * 2);
            ldsm4t(a1, mA + ((kk * 16 + aRow) * PK + wm * 32 + 16 + aCol8) * 2);
#pragma unroll
            for (int ng = 0; ng < 4; ng++) {
                unsigned bb[4];
                ldsm4t(bb, nB + ((kk * 16 + bRow) * PK + wn * 64 + ng * 16 + bCol8) * 2);
                mma16816(c + (2 * ng + 0) * 4,     a0, bb);
                mma16816(c + (2 * ng + 1) * 4,     a0, bb + 2);
                mma16816(c + (8 + 2 * ng + 0) * 4, a1, bb);
                mma16816(c + (8 + 2 * ng + 1) * 4, a1, bb + 2);
            }
        }
    }

#pragma unroll
    for (int j = 0; j < 8; j++) atomicAdd(&scnt[mcol + j], cnt[j]);
    // drain wrapped dead node groups: phase-2 stages reuse this smem
    asm volatile("cp.async.wait_group 0;" ::: "memory");
    __syncthreads();   // scnt valid; phase-1 smem dead

    // --- phase-2 prologue: overlap loads with P normalize/store ---
    const float* selfF = nodes + ((long long)b * SEQ + i0 + (t >> 1)) * DIM + (t & 1) * 8;
    float4 s0a = *(const float4*)(selfF + 0);
    float4 s0b = *(const float4*)(selfF + 4);
    float4 s1a = *(const float4*)(selfF + 16);
    float4 s1b = *(const float4*)(selfF + 20);
    ISSUE_W(0);
    ISSUE_W(1);

    // normalize P (2D fragment layout) and store bf16 to P region
    {
        const int rBase = wm * 32 + (lane >> 2);
        const float i00 = 1.f / fmaxf((float)scnt[rBase], 1.f);
        const float i01 = 1.f / fmaxf((float)scnt[rBase + 8], 1.f);
        const float i10 = 1.f / fmaxf((float)scnt[rBase + 16], 1.f);
        const float i11 = 1.f / fmaxf((float)scnt[rBase + 24], 1.f);
        unsigned char* P = smem + OFF_P;
        const int colB = wn * 64 + 2 * (lane & 3);
#pragma unroll
        for (int mt = 0; mt < 2; mt++) {
            const float ivA = mt ? i10 : i00;
            const float ivB = mt ? i11 : i01;
            const int r0 = rBase + mt * 16;
#pragma unroll
            for (int nn = 0; nn < 8; nn++) {
                float* cc = c + (mt * 8 + nn) * 4;
                const int col = colB + nn * 8;
                *(unsigned*)(P + (r0 * PK + col) * 2)       = packbf(cc[0] * ivA, cc[1] * ivA);
                *(unsigned*)(P + ((r0 + 8) * PK + col) * 2) = packbf(cc[2] * ivB, cc[3] * ivB);
            }
        }
    }
    STS_SELF(0, s0a, s0b);
    STS_SELF(1, s1a, s1b);

    // ---- phase 2: out = P@W + selfH@Bh + selfH@Bl + selfL@Bh ----
#pragma unroll
    for (int i = 0; i < 64; i++) c[i] = 0.f;

    const unsigned aS2     = ((wid * 16 + (lane & 15)) * 24 + ((lane >> 4) & 1) * 8) * 2;
    const unsigned aP_base = ((wid * 16 + (lane & 15)) * PK + ((lane >> 4) & 1) * 8) * 2;
    const unsigned Psm = maskSm + OFF_P;

    float4 pa, pb;
#pragma unroll 1
    for (int jc = 0; jc < NCH; ++jc) {
        if (jc == NCH - 1) asm volatile("cp.async.wait_group 0;" ::: "memory");
        else               asm volatile("cp.async.wait_group 1;" ::: "memory");
        __syncthreads();   // chunk jc (cp.async + self STS) visible

        if (jc + 2 < NCH) {
            pa = *(const float4*)(selfF + (jc + 2) * CH);
            pb = *(const float4*)(selfF + (jc + 2) * CH + 4);
        }

        const unsigned st = maskSm + (jc & 1) * STGSZ;
        unsigned aH[4], aL[4], aP[4];
        ldsm4(aH, st + C_SH + aS2);
        ldsm4(aL, st + C_SL + aS2);
        ldsm4(aP, Psm + aP_base + jc * CH * 2);
#pragma unroll
        for (int nb = 0; nb < 8; nb++) {
            const unsigned off = bOff + nb * 16 * 2;
            unsigned bW[4], bH[4], bL[4];
            ldsm4t(bW, st + C_W  + off);
            ldsm4t(bH, st + C_BH + off);
            ldsm4t(bL, st + C_BL + off);
            float* cc0 = c + 8 * nb;
            float* cc1 = c + 8 * nb + 4;
            mma16816(cc0, aP, bW);  mma16816(cc1, aP, bW + 2);
            mma16816(cc0, aH, bH);  mma16816(cc1, aH, bH + 2);
            mma16816(cc0, aH, bL);  mma16816(cc1, aH, bL + 2);
            mma16816(cc0, aL, bH);  mma16816(cc1, aL, bH + 2);
        }
        __syncthreads();   // stage (jc&1) free for reuse
        if (jc + 2 < NCH) {
            ISSUE_W(jc + 2);
            STS_SELF(jc + 2, pa, pb);
        }
    }

    const int orow = i0 + wid * 16 + (lane >> 2);
    const int ocol = 2 * (lane & 3);
    float* outB = out + ((long long)b * SEQ + orow) * DIM;
#pragma unroll
    for (int nt = 0; nt < 16; nt++) {
        int colx = 8 * nt + ocol;
        float2 v01 = make_float2(lrelu(c[4 * nt + 0]), lrelu(c[4 * nt + 1]));
        float2 v23 = make_float2(lrelu(c[4 * nt + 2]), lrelu(c[4 * nt + 3]));
        *(float2*)(outB + colx)           = v01;
        *(float2*)(outB + 8 * DIM + colx) = v23;
    }
}

extern "C" void kernel_launch(void* const* d_in, const int* in_sizes, int n_in,
                              void* d_out, int out_size)
{
    (void)in_sizes; (void)n_in; (void)out_size;
    const float* nodes = (const float*)d_in[0];
    const int*   adj   = (const int*)d_in[1];
    const float* Wm    = (const float*)d_in[2];
    const float* Bm    = (const float*)d_in[3];
    float*       out   = (float*)d_out;

    cudaFuncSetAttribute(gcn_fused_kernel,
                         cudaFuncAttributeMaxDynamicSharedMemorySize, SMEM_SZ);

    prep_all<<<1056, 256>>>(nodes, Wm, Bm);
    dim3 grid(SEQ / 128, BATCHN);
    gcn_fused_kernel<<<grid, 256, SMEM_SZ>>>(nodes, adj, out);
}